// round 3
// baseline (speedup 1.0000x reference)
#include <cuda_runtime.h>
#include <math.h>

// ---------------- problem constants ----------------
#define BB    32
#define TT1   2048
#define TT2   512
#define NMEL  80
#define NATT  80
#define NTEXT 512
#define NSPK  512
#define TEMP  0.0005f
#define NEGINF -1e9f

// ---------------- scratch (static device memory; no allocs) ----------------
__device__ float g_kspk[BB * NTEXT];          // [B,512]
__device__ float g_qspk[BB * NMEL];           // [B,80]
__device__ float g_kmid[BB * 1024 * TT2];     // [B,1024,512]  64 MB
__device__ float g_kenc[BB * NATT * TT2];     // [B,80,512]
__device__ float g_qmid1[BB * 160 * TT1];     // [B,160,2048]  40 MB
__device__ float g_qmid2[BB * NMEL * TT1];    // [B,80,2048]
__device__ float g_qenc[BB * NATT * TT1];     // [B,80,2048]
__device__ float g_k2[BB * TT2];
__device__ float g_q2[BB * TT1];

// ---------------- speaker linear: out[b,c] = spk[b,:] . W[c,:] + bias[c] ----
__global__ void spkproj_kernel(const float* __restrict__ spk,
                               const float* __restrict__ W,
                               const float* __restrict__ bias,
                               float* __restrict__ out, int Cout) {
    int c = blockIdx.x;
    int b = blockIdx.y;
    int l = threadIdx.x;
    const float* s = spk + (size_t)b * NSPK;
    const float* w = W + (size_t)c * NSPK;
    float acc = 0.f;
    for (int i = l; i < NSPK; i += 32) acc += s[i] * w[i];
    #pragma unroll
    for (int o = 16; o > 0; o >>= 1) acc += __shfl_xor_sync(0xffffffffu, acc, o);
    if (l == 0) out[b * Cout + c] = acc + bias[c];
}

// ---------------- conv1d-as-GEMM (tiled, fp32) -----------------------------
// Y[b,co,t] = bias[co] + sum_{ci,d} W[co,ci,d] * (X[b,ci,t+d-pad] + addvec[b,ci])
// padding contributes exact zeros (speaker add applied pre-padding, as in ref).
template <int TM, int TN, int TK, int RM, int RN, bool RELU>
__global__ void convgemm_kernel(const float* __restrict__ W,
                                const float* __restrict__ bias,
                                const float* __restrict__ X,
                                const float* __restrict__ addvec,
                                float* __restrict__ Y,
                                int Cout, int Cin, int T, int ks) {
    __shared__ __align__(16) float As[TK][TM];
    __shared__ __align__(16) float Bs[TK][TN];
    constexpr int NT = (TM / RM) * (TN / RN);   // threads per block

    const int b = blockIdx.z;
    const int mBase = blockIdx.y * TM;
    const int tBase = blockIdx.x * TN;
    const int KK = Cin * ks;
    const int pad = (ks - 1) / 2;
    const float* Xb = X + (size_t)b * Cin * T;
    const float* av = addvec ? addvec + (size_t)b * Cin : nullptr;

    const int tid = threadIdx.x;
    const int mt = tid % (TM / RM);
    const int nt = tid / (TM / RM);
    const int m0 = mt * RM;
    const int n0 = nt * RN;

    float acc[RM][RN];
    #pragma unroll
    for (int i = 0; i < RM; ++i)
        #pragma unroll
        for (int j = 0; j < RN; ++j) acc[i][j] = 0.f;

    for (int kb = 0; kb < KK; kb += TK) {
        // load weight tile (transposed into As[k][m])
        for (int idx = tid; idx < TM * TK; idx += NT) {
            int m = idx / TK, k = idx % TK;
            int row = mBase + m;
            As[k][m] = (row < Cout) ? W[(size_t)row * KK + kb + k] : 0.f;
        }
        // load im2col input tile
        for (int idx = tid; idx < TK * TN; idx += NT) {
            int k = idx / TN, n = idx % TN;
            int kk = kb + k;
            int ci = kk / ks, d = kk - ci * ks;
            int tt = tBase + n + d - pad;
            float v = 0.f;
            if (tt >= 0 && tt < T) {
                v = Xb[(size_t)ci * T + tt];
                if (av) v += av[ci];
            }
            Bs[k][n] = v;
        }
        __syncthreads();
        #pragma unroll
        for (int k = 0; k < TK; ++k) {
            float aR[RM], bR[RN];
            #pragma unroll
            for (int i = 0; i < RM; i += 4)
                *reinterpret_cast<float4*>(&aR[i]) =
                    *reinterpret_cast<const float4*>(&As[k][m0 + i]);
            #pragma unroll
            for (int j = 0; j < RN; j += 4)
                *reinterpret_cast<float4*>(&bR[j]) =
                    *reinterpret_cast<const float4*>(&Bs[k][n0 + j]);
            #pragma unroll
            for (int i = 0; i < RM; ++i)
                #pragma unroll
                for (int j = 0; j < RN; ++j)
                    acc[i][j] = fmaf(aR[i], bR[j], acc[i][j]);
        }
        __syncthreads();
    }

    #pragma unroll
    for (int i = 0; i < RM; ++i) {
        int row = mBase + m0 + i;
        if (row >= Cout) continue;
        float bv = bias[row];
        float* yrow = Y + ((size_t)b * Cout + row) * T + tBase + n0;
        #pragma unroll
        for (int j = 0; j < RN; j += 4) {
            float4 o;
            o.x = acc[i][j + 0] + bv;
            o.y = acc[i][j + 1] + bv;
            o.z = acc[i][j + 2] + bv;
            o.w = acc[i][j + 3] + bv;
            if (RELU) {
                o.x = fmaxf(o.x, 0.f); o.y = fmaxf(o.y, 0.f);
                o.z = fmaxf(o.z, 0.f); o.w = fmaxf(o.w, 0.f);
            }
            *reinterpret_cast<float4*>(&yrow[j]) = o;
        }
    }
}

// ---------------- channel-wise sum of squares: out[b,t] = sum_c X[b,c,t]^2 --
__global__ void sumsq_kernel(const float* __restrict__ X, float* __restrict__ out,
                             int C, int T) {
    int b = blockIdx.y;
    int t = blockIdx.x * blockDim.x + threadIdx.x;
    if (t >= T) return;
    const float* p = X + (size_t)b * C * T + t;
    float s = 0.f;
    for (int c = 0; c < C; ++c) {
        float v = p[(size_t)c * T];
        s = fmaf(v, v, s);
    }
    out[b * T + t] = s;
}

// ---------------- fused attention tail --------------------------------------
// For 32 query rows per block: logits = -TEMP*(|q|^2+|k|^2-2 q.k) over T2=512,
// log_softmax, +log(prior+1e-8) -> outLP; mask -> NEG_INF; softmax -> outA.
// Column ownership per lane l: col = 128*g + 4*l + e (g=0..3, e=0..3) so every
// LDS.128 / LDG.128 / STG.128 is lane-stride-1 (conflict-free & coalesced).
__global__ void attn_kernel(const float* __restrict__ qenc,
                            const float* __restrict__ kenc,
                            const float* __restrict__ q2,
                            const float* __restrict__ k2,
                            const float* __restrict__ prior,
                            const int* __restrict__ mask,
                            float* __restrict__ outA,
                            float* __restrict__ outLP) {
    extern __shared__ __align__(16) float sm[];
    float* ks_s = sm;                          // [80][512]
    float* qs   = ks_s + NATT * TT2;           // [80][32]
    float* k2s  = qs + NATT * 32;              // [512]
    float* q2s  = k2s + TT2;                   // [32]
    int*   ms   = (int*)(q2s + 32);            // [512]

    const int b = blockIdx.y;
    const int t1Base = blockIdx.x * 32;
    const int tid = threadIdx.x;

    {   // stage keys_enc, query tile, norms, mask
        const float4* src = reinterpret_cast<const float4*>(kenc + (size_t)b * NATT * TT2);
        float4* dst = reinterpret_cast<float4*>(ks_s);
        for (int i = tid; i < NATT * TT2 / 4; i += 256) dst[i] = src[i];
        for (int i = tid; i < NATT * 32; i += 256) {
            int c = i / 32, r = i % 32;
            qs[i] = qenc[((size_t)b * NATT + c) * TT1 + t1Base + r];
        }
        for (int i = tid; i < TT2; i += 256) k2s[i] = k2[b * TT2 + i];
        if (tid < 32) q2s[tid] = q2[b * TT1 + t1Base + tid];
        for (int i = tid; i < TT2; i += 256) ms[i] = mask[b * TT2 + i];
    }
    __syncthreads();

    const int w = tid >> 5, l = tid & 31;
    const int r0 = w * 4;                      // this warp owns rows r0..r0+3

    float acc[4][16];
    #pragma unroll
    for (int r = 0; r < 4; ++r)
        #pragma unroll
        for (int j = 0; j < 16; ++j) acc[r][j] = 0.f;

    for (int c = 0; c < NATT; ++c) {
        float4 q4 = *reinterpret_cast<const float4*>(&qs[c * 32 + r0]);  // broadcast
        float qv[4] = {q4.x, q4.y, q4.z, q4.w};
        #pragma unroll
        for (int g = 0; g < 4; ++g) {
            float4 kv = *reinterpret_cast<const float4*>(&ks_s[c * TT2 + g * 128 + l * 4]);
            #pragma unroll
            for (int r = 0; r < 4; ++r) {
                acc[r][g * 4 + 0] = fmaf(qv[r], kv.x, acc[r][g * 4 + 0]);
                acc[r][g * 4 + 1] = fmaf(qv[r], kv.y, acc[r][g * 4 + 1]);
                acc[r][g * 4 + 2] = fmaf(qv[r], kv.z, acc[r][g * 4 + 2]);
                acc[r][g * 4 + 3] = fmaf(qv[r], kv.w, acc[r][g * 4 + 3]);
            }
        }
    }

    // per-lane column constants
    float k2r[16];
    int mr[16];
    #pragma unroll
    for (int g = 0; g < 4; ++g) {
        float4 kk = *reinterpret_cast<const float4*>(&k2s[g * 128 + l * 4]);
        k2r[g * 4 + 0] = kk.x; k2r[g * 4 + 1] = kk.y;
        k2r[g * 4 + 2] = kk.z; k2r[g * 4 + 3] = kk.w;
        #pragma unroll
        for (int e = 0; e < 4; ++e) mr[g * 4 + e] = ms[g * 128 + l * 4 + e];
    }

    for (int r = 0; r < 4; ++r) {
        const int t1 = t1Base + r0 + r;
        const float q2v = q2s[r0 + r];

        float lg[16];
        float mx = -3.4e38f;
        #pragma unroll
        for (int j = 0; j < 16; ++j) {
            lg[j] = -TEMP * (q2v + k2r[j] - 2.f * acc[r][j]);
            mx = fmaxf(mx, lg[j]);
        }
        #pragma unroll
        for (int o = 16; o > 0; o >>= 1)
            mx = fmaxf(mx, __shfl_xor_sync(0xffffffffu, mx, o));
        float sum = 0.f;
        #pragma unroll
        for (int j = 0; j < 16; ++j) sum += expf(lg[j] - mx);
        #pragma unroll
        for (int o = 16; o > 0; o >>= 1)
            sum += __shfl_xor_sync(0xffffffffu, sum, o);
        const float lse = mx + logf(sum);

        const float* pr = prior + ((size_t)b * TT1 + t1) * TT2;
        float* olp = outLP + ((size_t)b * TT1 + t1) * TT2;
        float lp[16];
        #pragma unroll
        for (int g = 0; g < 4; ++g) {
            float4 p4 = *reinterpret_cast<const float4*>(&pr[g * 128 + l * 4]);
            lp[g * 4 + 0] = lg[g * 4 + 0] - lse + logf(p4.x + 1e-8f);
            lp[g * 4 + 1] = lg[g * 4 + 1] - lse + logf(p4.y + 1e-8f);
            lp[g * 4 + 2] = lg[g * 4 + 2] - lse + logf(p4.z + 1e-8f);
            lp[g * 4 + 3] = lg[g * 4 + 3] - lse + logf(p4.w + 1e-8f);
            float4 o;
            o.x = lp[g * 4 + 0]; o.y = lp[g * 4 + 1];
            o.z = lp[g * 4 + 2]; o.w = lp[g * 4 + 3];
            *reinterpret_cast<float4*>(&olp[g * 128 + l * 4]) = o;
        }

        // masked softmax
        float v[16];
        float mx2 = -3.4e38f;
        #pragma unroll
        for (int j = 0; j < 16; ++j) {
            v[j] = mr[j] ? NEGINF : lp[j];
            mx2 = fmaxf(mx2, v[j]);
        }
        #pragma unroll
        for (int o = 16; o > 0; o >>= 1)
            mx2 = fmaxf(mx2, __shfl_xor_sync(0xffffffffu, mx2, o));
        float s2 = 0.f;
        #pragma unroll
        for (int j = 0; j < 16; ++j) {
            v[j] = expf(v[j] - mx2);   // masked -> expf(~-1e9) == 0 exactly
            s2 += v[j];
        }
        #pragma unroll
        for (int o = 16; o > 0; o >>= 1)
            s2 += __shfl_xor_sync(0xffffffffu, s2, o);
        const float inv = 1.f / s2;

        float* oa = outA + ((size_t)b * TT1 + t1) * TT2;
        #pragma unroll
        for (int g = 0; g < 4; ++g) {
            float4 o;
            o.x = v[g * 4 + 0] * inv; o.y = v[g * 4 + 1] * inv;
            o.z = v[g * 4 + 2] * inv; o.w = v[g * 4 + 3] * inv;
            *reinterpret_cast<float4*>(&oa[g * 128 + l * 4]) = o;
        }
    }
}

// ---------------- launch ----------------------------------------------------
extern "C" void kernel_launch(void* const* d_in, const int* in_sizes, int n_in,
                              void* d_out, int out_size) {
    const float* queries   = (const float*)d_in[0];   // [32,80,2048]
    const float* keys      = (const float*)d_in[1];   // [32,512,512]
    const int*   mask      = (const int*)d_in[2];     // [32,512,1] bool -> int32
    const float* prior     = (const float*)d_in[3];   // [32,2048,512]
    const float* spk       = (const float*)d_in[4];   // [32,512]
    const float* kw1 = (const float*)d_in[5];
    const float* kb1 = (const float*)d_in[6];
    const float* kw2 = (const float*)d_in[7];
    const float* kb2 = (const float*)d_in[8];
    const float* qw1 = (const float*)d_in[9];
    const float* qb1 = (const float*)d_in[10];
    const float* qw2 = (const float*)d_in[11];
    const float* qb2 = (const float*)d_in[12];
    const float* qw3 = (const float*)d_in[13];
    const float* qb3 = (const float*)d_in[14];
    const float* kspk_w = (const float*)d_in[15];
    const float* kspk_b = (const float*)d_in[16];
    const float* qspk_w = (const float*)d_in[17];
    const float* qspk_b = (const float*)d_in[18];

    float* outA  = (float*)d_out;                               // attn
    float* outLP = (float*)d_out + (size_t)BB * TT1 * TT2;      // attn_logprob

    float *kspk, *qspk, *kmid, *kenc, *qmid1, *qmid2, *qenc, *k2, *q2;
    cudaGetSymbolAddress((void**)&kspk,  g_kspk);
    cudaGetSymbolAddress((void**)&qspk,  g_qspk);
    cudaGetSymbolAddress((void**)&kmid,  g_kmid);
    cudaGetSymbolAddress((void**)&kenc,  g_kenc);
    cudaGetSymbolAddress((void**)&qmid1, g_qmid1);
    cudaGetSymbolAddress((void**)&qmid2, g_qmid2);
    cudaGetSymbolAddress((void**)&qenc,  g_qenc);
    cudaGetSymbolAddress((void**)&k2,    g_k2);
    cudaGetSymbolAddress((void**)&q2,    g_q2);

    // attention tail needs >48KB dynamic smem; set attribute every call
    // (deterministic, no static guards; non-stream API, capture-safe)
    size_t smem = (size_t)(NATT * TT2 + NATT * 32 + TT2 + 32) * sizeof(float)
                + TT2 * sizeof(int);
    cudaFuncSetAttribute(attn_kernel, cudaFuncAttributeMaxDynamicSharedMemorySize,
                         (int)smem);

    // 1. speaker projections
    spkproj_kernel<<<dim3(NTEXT, BB), 32>>>(spk, kspk_w, kspk_b, kspk, NTEXT);
    spkproj_kernel<<<dim3(NMEL, BB), 32>>>(spk, qspk_w, qspk_b, qspk, NMEL);

    // 2. keys conv1 (512->1024, k3) + relu   [dominant GEMM]
    convgemm_kernel<128, 64, 16, 8, 4, true>
        <<<dim3(TT2 / 64, 1024 / 128, BB), 256>>>(
            kw1, kb1, keys, kspk, kmid, 1024, NTEXT, TT2, 3);

    // 3. keys conv2 (1024->80, k1)
    convgemm_kernel<64, 64, 16, 4, 4, false>
        <<<dim3(TT2 / 64, 2, BB), 256>>>(
            kw2, kb2, kmid, nullptr, kenc, NATT, 1024, TT2, 1);

    // 4. queries conv1 (80->160, k3) + relu
    convgemm_kernel<64, 64, 16, 4, 4, true>
        <<<dim3(TT1 / 64, 3, BB), 256>>>(
            qw1, qb1, queries, qspk, qmid1, 160, NMEL, TT1, 3);

    // 5. queries conv2 (160->80, k1) + relu
    convgemm_kernel<64, 64, 16, 4, 4, true>
        <<<dim3(TT1 / 64, 2, BB), 256>>>(
            qw2, qb2, qmid1, nullptr, qmid2, NMEL, 160, TT1, 1);

    // 6. queries conv3 (80->80, k1)
    convgemm_kernel<64, 64, 16, 4, 4, false>
        <<<dim3(TT1 / 64, 2, BB), 256>>>(
            qw3, qb3, qmid2, nullptr, qenc, NATT, NMEL, TT1, 1);

    // 7. squared norms
    sumsq_kernel<<<dim3(TT2 / 256, BB), 256>>>(kenc, k2, NATT, TT2);
    sumsq_kernel<<<dim3(TT1 / 256, BB), 256>>>(qenc, q2, NATT, TT1);

    // 8. fused attention tail
    attn_kernel<<<dim3(TT1 / 32, BB), 256, smem>>>(
        qenc, kenc, q2, k2, prior, mask, outA, outLP);
}

// round 6
// speedup vs baseline: 3.0221x; 3.0221x over previous
#include <cuda_runtime.h>
#include <math.h>
#include <stdint.h>

// ---------------- problem constants ----------------
#define BB    32
#define TT1   2048
#define TT2   512
#define NMEL  80
#define NATT  80
#define NTEXT 512
#define NSPK  512
#define TEMP  0.0005f

// ---------------- scratch (static device memory; no allocs) ----------------
__device__ float g_kspk[BB * NTEXT];
__device__ float g_qspk[BB * NMEL];
__device__ float g_kmid[BB * 1024 * TT2];
__device__ float g_kenc[BB * NATT * TT2];
__device__ float g_qmid1[BB * 160 * TT1];
__device__ float g_qmid2[BB * NMEL * TT1];
__device__ float g_qenc[BB * NATT * TT1];
__device__ float g_k2[BB * TT2];
__device__ float g_q2[BB * TT1];

// ---------------- helpers ---------------------------------------------------
__device__ __forceinline__ float to_tf32(float x) {
    unsigned u;
    asm("cvt.rna.tf32.f32 %0, %1;" : "=r"(u) : "f"(x));
    return __uint_as_float(u);
}

__device__ __forceinline__ void mma_tf32(float d[4], const float a[4], const float b[2]) {
    asm volatile(
        "mma.sync.aligned.m16n8k8.row.col.f32.tf32.tf32.f32 "
        "{%0,%1,%2,%3}, {%4,%5,%6,%7}, {%8,%9}, {%0,%1,%2,%3};\n"
        : "+f"(d[0]), "+f"(d[1]), "+f"(d[2]), "+f"(d[3])
        : "r"(__float_as_uint(a[0])), "r"(__float_as_uint(a[1])),
          "r"(__float_as_uint(a[2])), "r"(__float_as_uint(a[3])),
          "r"(__float_as_uint(b[0])), "r"(__float_as_uint(b[1])));
}

// ---------------- speaker linear --------------------------------------------
__global__ void spkproj_kernel(const float* __restrict__ spk,
                               const float* __restrict__ W,
                               const float* __restrict__ bias,
                               float* __restrict__ out, int Cout) {
    int c = blockIdx.x, b = blockIdx.y, l = threadIdx.x;
    const float* s = spk + (size_t)b * NSPK;
    const float* w = W + (size_t)c * NSPK;
    float acc = 0.f;
    for (int i = l; i < NSPK; i += 32) acc += s[i] * w[i];
    #pragma unroll
    for (int o = 16; o > 0; o >>= 1) acc += __shfl_xor_sync(0xffffffffu, acc, o);
    if (l == 0) out[b * Cout + c] = acc + bias[c];
}

// ---------------- tf32 tensor-core conv1d-as-GEMM ---------------------------
// Y[b,co,t] = bias + sum_{ci,d} W[co,ci,d]*(X[b,ci,t+d-pad] + addvec[b,ci])
// Block tile 128x64, BK=32. 8 warps: warp grid 4(M) x 2(N), warp tile 32x32.
// A smem: [128][36] padded (frag LDS conflict-free).
// B smem: [32][64], column swizzle n ^ (8*(k&3)) (frag LDS conflict-free).
#define CBM 128
#define CBN 64
#define CBK 32
#define AKP 36

template <int KS, bool RELU>
__global__ __launch_bounds__(256)
void mma_convgemm(const float* __restrict__ W, const float* __restrict__ bias,
                  const float* __restrict__ X, const float* __restrict__ addvec,
                  float* __restrict__ Y, int Cout, int Cin, int T) {
    __shared__ __align__(16) float As[CBM][AKP];
    __shared__ __align__(16) float Bs[CBK][CBN];

    const int b = blockIdx.z;
    const int mBase = blockIdx.y * CBM;
    const int tBase = blockIdx.x * CBN;
    const int KK = Cin * KS;
    const int pad = (KS - 1) >> 1;
    const float* Xb = X + (size_t)b * Cin * T;
    const float* av = addvec ? addvec + (size_t)b * Cin : nullptr;

    const int tid = threadIdx.x;
    const int lane = tid & 31;
    const int warp = tid >> 5;
    const int wm = (warp & 3) * 32;
    const int wn = (warp >> 2) * 32;
    const int gid = lane >> 2;   // 0..7
    const int tig = lane & 3;    // 0..3

    // A staging: row = tid>>1, koff = (tid&1)*16 (4 float4 each)
    const int arow = tid >> 1;
    const int akoff = (tid & 1) * 16;
    // B staging: k = tid>>3, n0 = (tid&7)*8 (8 elems each)
    const int bk = tid >> 3;
    const int bn0 = (tid & 7) * 8;
    const int bswz = (bk & 3) * 8;

    float acc[2][4][4];
    #pragma unroll
    for (int mi = 0; mi < 2; ++mi)
        #pragma unroll
        for (int ni = 0; ni < 4; ++ni)
            #pragma unroll
            for (int r = 0; r < 4; ++r) acc[mi][ni][r] = 0.f;

    for (int kb = 0; kb < KK; kb += CBK) {
        // ---- stage A (weights, tf32) ----
        {
            const int grow = mBase + arow;
            const float* wrow = W + (size_t)grow * KK;
            #pragma unroll
            for (int v = 0; v < 4; ++v) {
                int kk = kb + akoff + v * 4;
                float4 w4 = make_float4(0.f, 0.f, 0.f, 0.f);
                if (grow < Cout && kk < KK)
                    w4 = *reinterpret_cast<const float4*>(&wrow[kk]);
                w4.x = to_tf32(w4.x); w4.y = to_tf32(w4.y);
                w4.z = to_tf32(w4.z); w4.w = to_tf32(w4.w);
                *reinterpret_cast<float4*>(&As[arow][akoff + v * 4]) = w4;
            }
        }
        // ---- stage B (im2col input + speaker add, tf32) ----
        {
            const int kk = kb + bk;
            const bool kval = kk < KK;
            int ci, d;
            if (KS == 1) { ci = kk; d = 0; }
            else         { ci = kk / KS; d = kk - ci * KS; }
            if (!kval) ci = 0;
            const float addv = (KS == 3 && av && kval) ? av[ci] : 0.f;
            const float* xr = Xb + (size_t)ci * T;
            const int tt0 = tBase + bn0 + d - pad;
            float vb[8];
            #pragma unroll
            for (int j = 0; j < 8; ++j) {
                int tt = tt0 + j;
                float v = 0.f;
                if (KS == 1) {
                    if (kval) v = xr[tt];
                } else {
                    if (kval && tt >= 0 && tt < T) v = xr[tt] + addv;
                }
                vb[j] = to_tf32(v);
            }
            float4 lo = make_float4(vb[0], vb[1], vb[2], vb[3]);
            float4 hi = make_float4(vb[4], vb[5], vb[6], vb[7]);
            *reinterpret_cast<float4*>(&Bs[bk][bn0 ^ bswz]) = lo;
            *reinterpret_cast<float4*>(&Bs[bk][(bn0 + 4) ^ bswz]) = hi;
        }
        __syncthreads();

        // ---- compute: 4 k8-steps ----
        #pragma unroll
        for (int s8 = 0; s8 < 4; ++s8) {
            const int k0 = s8 * 8;
            float a[2][4];
            #pragma unroll
            for (int mi = 0; mi < 2; ++mi) {
                const int r = wm + mi * 16 + gid;
                a[mi][0] = As[r][k0 + tig];
                a[mi][1] = As[r + 8][k0 + tig];
                a[mi][2] = As[r][k0 + tig + 4];
                a[mi][3] = As[r + 8][k0 + tig + 4];
            }
            const int fswz = tig * 8;     // swizzle for rows k0+tig and k0+tig+4
            #pragma unroll
            for (int ni = 0; ni < 4; ++ni) {
                float bf[2];
                const int n = wn + ni * 8 + gid;
                bf[0] = Bs[k0 + tig][n ^ fswz];
                bf[1] = Bs[k0 + tig + 4][n ^ fswz];
                #pragma unroll
                for (int mi = 0; mi < 2; ++mi)
                    mma_tf32(acc[mi][ni], a[mi], bf);
            }
        }
        __syncthreads();
    }

    // ---- epilogue: bias (+relu), fp32 store ----
    #pragma unroll
    for (int mi = 0; mi < 2; ++mi) {
        const int r0 = mBase + wm + mi * 16 + gid;
        const int r1 = r0 + 8;
        const float bv0 = (r0 < Cout) ? bias[r0] : 0.f;
        const float bv1 = (r1 < Cout) ? bias[r1] : 0.f;
        #pragma unroll
        for (int ni = 0; ni < 4; ++ni) {
            const int c = tBase + wn + ni * 8 + tig * 2;
            if (r0 < Cout) {
                float2 o;
                o.x = acc[mi][ni][0] + bv0;
                o.y = acc[mi][ni][1] + bv0;
                if (RELU) { o.x = fmaxf(o.x, 0.f); o.y = fmaxf(o.y, 0.f); }
                *reinterpret_cast<float2*>(&Y[((size_t)b * Cout + r0) * T + c]) = o;
            }
            if (r1 < Cout) {
                float2 o;
                o.x = acc[mi][ni][2] + bv1;
                o.y = acc[mi][ni][3] + bv1;
                if (RELU) { o.x = fmaxf(o.x, 0.f); o.y = fmaxf(o.y, 0.f); }
                *reinterpret_cast<float2*>(&Y[((size_t)b * Cout + r1) * T + c]) = o;
            }
        }
    }
}

// ---------------- channel-wise sum of squares -------------------------------
__global__ void sumsq_kernel(const float* __restrict__ X, float* __restrict__ out,
                             int C, int T) {
    int b = blockIdx.y;
    int t = blockIdx.x * blockDim.x + threadIdx.x;
    if (t >= T) return;
    const float* p = X + (size_t)b * C * T + t;
    float s = 0.f;
    for (int c = 0; c < C; ++c) {
        float v = p[(size_t)c * T];
        s = fmaf(v, v, s);
    }
    out[b * T + t] = s;
}

// ---------------- fused attention tail --------------------------------------
// logits = -TEMP*(|q|^2+|k|^2-2 q.k); outLP = log_softmax + log(prior+1e-8);
// outA  = masked renorm of e_j*(prior_j+1e-8)   [algebraic 2nd softmax].
__global__ void attn_kernel(const float* __restrict__ qenc,
                            const float* __restrict__ kenc,
                            const float* __restrict__ q2,
                            const float* __restrict__ k2,
                            const float* __restrict__ prior,
                            const int* __restrict__ mask,
                            float* __restrict__ outA,
                            float* __restrict__ outLP) {
    extern __shared__ __align__(16) float sm[];
    float* ks_s = sm;                          // [80][512]
    float* qs   = ks_s + NATT * TT2;           // [80][32]
    float* k2s  = qs + NATT * 32;              // [512]
    float* q2s  = k2s + TT2;                   // [32]
    int*   ms   = (int*)(q2s + 32);            // [512]

    const int b = blockIdx.y;
    const int t1Base = blockIdx.x * 32;
    const int tid = threadIdx.x;

    {
        const float4* src = reinterpret_cast<const float4*>(kenc + (size_t)b * NATT * TT2);
        float4* dst = reinterpret_cast<float4*>(ks_s);
        for (int i = tid; i < NATT * TT2 / 4; i += 256) dst[i] = src[i];
        for (int i = tid; i < NATT * 32; i += 256) {
            int c = i / 32, r = i % 32;
            qs[i] = qenc[((size_t)b * NATT + c) * TT1 + t1Base + r];
        }
        for (int i = tid; i < TT2; i += 256) k2s[i] = k2[b * TT2 + i];
        if (tid < 32) q2s[tid] = q2[b * TT1 + t1Base + tid];
        for (int i = tid; i < TT2; i += 256) ms[i] = mask[b * TT2 + i];
    }
    __syncthreads();

    const int w = tid >> 5, l = tid & 31;
    const int r0 = w * 4;

    float acc[4][16];
    #pragma unroll
    for (int r = 0; r < 4; ++r)
        #pragma unroll
        for (int j = 0; j < 16; ++j) acc[r][j] = 0.f;

    for (int c = 0; c < NATT; ++c) {
        float4 q4 = *reinterpret_cast<const float4*>(&qs[c * 32 + r0]);
        float qv[4] = {q4.x, q4.y, q4.z, q4.w};
        #pragma unroll
        for (int g = 0; g < 4; ++g) {
            float4 kv = *reinterpret_cast<const float4*>(&ks_s[c * TT2 + g * 128 + l * 4]);
            #pragma unroll
            for (int r = 0; r < 4; ++r) {
                acc[r][g * 4 + 0] = fmaf(qv[r], kv.x, acc[r][g * 4 + 0]);
                acc[r][g * 4 + 1] = fmaf(qv[r], kv.y, acc[r][g * 4 + 1]);
                acc[r][g * 4 + 2] = fmaf(qv[r], kv.z, acc[r][g * 4 + 2]);
                acc[r][g * 4 + 3] = fmaf(qv[r], kv.w, acc[r][g * 4 + 3]);
            }
        }
    }

    float k2r[16];
    int mr[16];
    #pragma unroll
    for (int g = 0; g < 4; ++g) {
        float4 kk = *reinterpret_cast<const float4*>(&k2s[g * 128 + l * 4]);
        k2r[g * 4 + 0] = kk.x; k2r[g * 4 + 1] = kk.y;
        k2r[g * 4 + 2] = kk.z; k2r[g * 4 + 3] = kk.w;
        #pragma unroll
        for (int e = 0; e < 4; ++e) mr[g * 4 + e] = ms[g * 128 + l * 4 + e];
    }

    for (int r = 0; r < 4; ++r) {
        const int t1 = t1Base + r0 + r;
        const float q2v = q2s[r0 + r];

        float lg[16];
        float mx = -3.4e38f;
        #pragma unroll
        for (int j = 0; j < 16; ++j) {
            lg[j] = -TEMP * (q2v + k2r[j] - 2.f * acc[r][j]);
            mx = fmaxf(mx, lg[j]);
        }
        #pragma unroll
        for (int o = 16; o > 0; o >>= 1)
            mx = fmaxf(mx, __shfl_xor_sync(0xffffffffu, mx, o));

        float wv[16];
        float sum = 0.f;
        #pragma unroll
        for (int j = 0; j < 16; ++j) {
            lg[j] -= mx;
            wv[j] = __expf(lg[j]);
            sum += wv[j];
        }
        #pragma unroll
        for (int o = 16; o > 0; o >>= 1)
            sum += __shfl_xor_sync(0xffffffffu, sum, o);
        const float lsum = __logf(sum);   // lp = (lg - mx) - log(sum)

        const float* pr = prior + ((size_t)b * TT1 + t1) * TT2;
        float* olp = outLP + ((size_t)b * TT1 + t1) * TT2;
        #pragma unroll
        for (int g = 0; g < 4; ++g) {
            float4 p4 = *reinterpret_cast<const float4*>(&pr[g * 128 + l * 4]);
            float pa[4] = {p4.x + 1e-8f, p4.y + 1e-8f, p4.z + 1e-8f, p4.w + 1e-8f};
            float4 o;
            o.x = lg[g * 4 + 0] - lsum + __logf(pa[0]);
            o.y = lg[g * 4 + 1] - lsum + __logf(pa[1]);
            o.z = lg[g * 4 + 2] - lsum + __logf(pa[2]);
            o.w = lg[g * 4 + 3] - lsum + __logf(pa[3]);
            *reinterpret_cast<float4*>(&olp[g * 128 + l * 4]) = o;
            #pragma unroll
            for (int e = 0; e < 4; ++e) {
                int j = g * 4 + e;
                wv[j] = mr[j] ? 0.f : wv[j] * pa[e];
            }
        }

        float s2 = 0.f;
        #pragma unroll
        for (int j = 0; j < 16; ++j) s2 += wv[j];
        #pragma unroll
        for (int o = 16; o > 0; o >>= 1)
            s2 += __shfl_xor_sync(0xffffffffu, s2, o);
        const float inv = 1.f / s2;

        float* oa = outA + ((size_t)b * TT1 + t1) * TT2;
        #pragma unroll
        for (int g = 0; g < 4; ++g) {
            float4 o;
            o.x = wv[g * 4 + 0] * inv; o.y = wv[g * 4 + 1] * inv;
            o.z = wv[g * 4 + 2] * inv; o.w = wv[g * 4 + 3] * inv;
            *reinterpret_cast<float4*>(&oa[g * 128 + l * 4]) = o;
        }
    }
}

// ---------------- launch ----------------------------------------------------
extern "C" void kernel_launch(void* const* d_in, const int* in_sizes, int n_in,
                              void* d_out, int out_size) {
    const float* queries = (const float*)d_in[0];
    const float* keys    = (const float*)d_in[1];
    const int*   mask    = (const int*)d_in[2];
    const float* prior   = (const float*)d_in[3];
    const float* spk     = (const float*)d_in[4];
    const float* kw1 = (const float*)d_in[5];
    const float* kb1 = (const float*)d_in[6];
    const float* kw2 = (const float*)d_in[7];
    const float* kb2 = (const float*)d_in[8];
    const float* qw1 = (const float*)d_in[9];
    const float* qb1 = (const float*)d_in[10];
    const float* qw2 = (const float*)d_in[11];
    const float* qb2 = (const float*)d_in[12];
    const float* qw3 = (const float*)d_in[13];
    const float* qb3 = (const float*)d_in[14];
    const float* kspk_w = (const float*)d_in[15];
    const float* kspk_b = (const float*)d_in[16];
    const float* qspk_w = (const float*)d_in[17];
    const float* qspk_b = (const float*)d_in[18];

    float* outA  = (float*)d_out;
    float* outLP = (float*)d_out + (size_t)BB * TT1 * TT2;

    float *kspk, *qspk, *kmid, *kenc, *qmid1, *qmid2, *qenc, *k2, *q2;
    cudaGetSymbolAddress((void**)&kspk,  g_kspk);
    cudaGetSymbolAddress((void**)&qspk,  g_qspk);
    cudaGetSymbolAddress((void**)&kmid,  g_kmid);
    cudaGetSymbolAddress((void**)&kenc,  g_kenc);
    cudaGetSymbolAddress((void**)&qmid1, g_qmid1);
    cudaGetSymbolAddress((void**)&qmid2, g_qmid2);
    cudaGetSymbolAddress((void**)&qenc,  g_qenc);
    cudaGetSymbolAddress((void**)&k2,    g_k2);
    cudaGetSymbolAddress((void**)&q2,    g_q2);

    size_t smem = (size_t)(NATT * TT2 + NATT * 32 + TT2 + 32) * sizeof(float)
                + TT2 * sizeof(int);
    cudaFuncSetAttribute(attn_kernel, cudaFuncAttributeMaxDynamicSharedMemorySize,
                         (int)smem);

    // 1. speaker projections
    spkproj_kernel<<<dim3(NTEXT, BB), 32>>>(spk, kspk_w, kspk_b, kspk, NTEXT);
    spkproj_kernel<<<dim3(NMEL, BB), 32>>>(spk, qspk_w, qspk_b, qspk, NMEL);

    // 2. keys conv1 (512->1024, k3) + relu  [tf32 mma]
    mma_convgemm<3, true><<<dim3(TT2 / CBN, 8, BB), 256>>>(
        kw1, kb1, keys, kspk, kmid, 1024, NTEXT, TT2);

    // 3. keys conv2 (1024->80, k1)
    mma_convgemm<1, false><<<dim3(TT2 / CBN, 1, BB), 256>>>(
        kw2, kb2, kmid, nullptr, kenc, NATT, 1024, TT2);

    // 4. queries conv1 (80->160, k3) + relu
    mma_convgemm<3, true><<<dim3(TT1 / CBN, 2, BB), 256>>>(
        qw1, qb1, queries, qspk, qmid1, 160, NMEL, TT1);

    // 5. queries conv2 (160->80, k1) + relu
    mma_convgemm<1, true><<<dim3(TT1 / CBN, 1, BB), 256>>>(
        qw2, qb2, qmid1, nullptr, qmid2, NMEL, 160, TT1);

    // 6. queries conv3 (80->80, k1)
    mma_convgemm<1, false><<<dim3(TT1 / CBN, 1, BB), 256>>>(
        qw3, qb3, qmid2, nullptr, qenc, NATT, NMEL, TT1);

    // 7. squared norms
    sumsq_kernel<<<dim3(TT2 / 256, BB), 256>>>(kenc, k2, NATT, TT2);
    sumsq_kernel<<<dim3(TT1 / 256, BB), 256>>>(qenc, q2, NATT, TT1);

    // 8. fused attention tail
    attn_kernel<<<dim3(TT1 / 32, BB), 256, smem>>>(
        qenc, kenc, q2, k2, prior, mask, outA, outLP);
}